// round 13
// baseline (speedup 1.0000x reference)
#include <cuda_runtime.h>
#include <cuda_fp16.h>
#include <cuda_bf16.h>
#include <math_constants.h>
#include <mma.h>
#include <cstdint>

using namespace nvcuda;

#define D     128
#define NMAX  50000
#define EMAX  1600000

// ---------------- device scratch (allocation-free, static) ----------------
__device__ int g_is64;
__device__ int g_src[EMAX];
__device__ int g_dst[EMAX];
__device__ __align__(16) int g_deg[NMAX + 4];
__device__ __align__(16) int g_start[NMAX + 4];
__device__ __align__(16) int g_cursor[NMAX + 4];
__device__ int g_csr_src[EMAX];

__device__ __align__(256) float  g_Q[(size_t)NMAX * D];      // [N,128] fp32
// fp16 K|V lane-interleaved: row = 32 chunks of 16B; chunk i = {K[4i..4i+3], V[4i..4i+3]}
__device__ __align__(256) __half g_KVh[(size_t)NMAX * 256];  // 512 B/row
__device__ __align__(256) float  g_H[(size_t)NMAX * D];      // layer-1 output

// ---------------- zero degree histogram + edge width detection (fused) ----
__global__ void k_init_csr(const unsigned* __restrict__ ei, int N) {
    int i = blockIdx.x * blockDim.x + threadIdx.x;
    if (i < N) g_deg[i] = 0;
    if (i == 0) {
        int is64 = 1;
        for (int j = 0; j < 64; j++)
            if (ei[2 * j + 1] != 0u) is64 = 0;
        g_is64 = is64;
    }
}

__global__ void k_convert(const void* __restrict__ ei, int E) {
    int i = blockIdx.x * blockDim.x + threadIdx.x;
    if (i >= E) return;
    int s, d;
    if (g_is64) {
        const long long* p = (const long long*)ei;
        s = (int)p[i];
        d = (int)p[(size_t)E + i];
    } else {
        const int* p = (const int*)ei;
        s = p[i];
        d = p[E + i];
    }
    g_src[i] = s;
    g_dst[i] = d;
    atomicAdd(&g_deg[d], 1);
}

// ---------------- fast single-block exclusive scan ----------------
__global__ void k_scan(int N) {
    __shared__ int warp_sums[32];
    __shared__ int s_carry;
    int tid = threadIdx.x, lane = tid & 31, wid = tid >> 5;
    if (tid == 0) s_carry = 0;
    __syncthreads();

    const int TILE = 4096;
    for (int base = 0; base < N; base += TILE) {
        int idx = base + tid * 4;
        int4 v = make_int4(0, 0, 0, 0);
        if (idx + 3 < N) v = *(const int4*)&g_deg[idx];
        else {
            if (idx + 0 < N) v.x = g_deg[idx + 0];
            if (idx + 1 < N) v.y = g_deg[idx + 1];
            if (idx + 2 < N) v.z = g_deg[idx + 2];
            if (idx + 3 < N) v.w = g_deg[idx + 3];
        }
        int t0 = v.x, t1 = t0 + v.y, t2 = t1 + v.z, t3 = t2 + v.w;
        int inc = t3;
#pragma unroll
        for (int o = 1; o < 32; o <<= 1) {
            int n = __shfl_up_sync(0xFFFFFFFFu, inc, o);
            if (lane >= o) inc += n;
        }
        if (lane == 31) warp_sums[wid] = inc;
        __syncthreads();
        if (wid == 0) {
            int ws = warp_sums[lane];
#pragma unroll
            for (int o = 1; o < 32; o <<= 1) {
                int n = __shfl_up_sync(0xFFFFFFFFu, ws, o);
                if (lane >= o) ws += n;
            }
            warp_sums[lane] = ws;
        }
        __syncthreads();
        int warp_off = wid ? warp_sums[wid - 1] : 0;
        int e0 = s_carry + warp_off + (inc - t3);
        int tile_total = warp_sums[31];

        if (idx + 3 < N) {
            int4 e = make_int4(e0, e0 + t0, e0 + t1, e0 + t2);
            *(int4*)&g_start[idx]  = e;
            *(int4*)&g_cursor[idx] = e;
        } else {
            if (idx + 0 < N) { g_start[idx + 0] = e0;      g_cursor[idx + 0] = e0;      }
            if (idx + 1 < N) { g_start[idx + 1] = e0 + t0; g_cursor[idx + 1] = e0 + t0; }
            if (idx + 2 < N) { g_start[idx + 2] = e0 + t1; g_cursor[idx + 2] = e0 + t1; }
            if (idx + 3 < N) { g_start[idx + 3] = e0 + t2; g_cursor[idx + 3] = e0 + t2; }
        }
        __syncthreads();
        if (tid == 0) s_carry += tile_total;
        __syncthreads();
    }
    if (tid == 0) g_start[N] = s_carry;
}

__global__ void k_scatter(int E) {
    int i = blockIdx.x * blockDim.x + threadIdx.x;
    if (i >= E) return;
    int d = g_dst[i];
    int pos = atomicAdd(&g_cursor[d], 1);
    g_csr_src[pos] = g_src[i];
}

// ---------------- wmma bf16 3-term split GEMM: C = X @ W^T + b -----------
// 128x128 tile, 256 thr (8 warps, warp = 16 rows x 128 cols).
// X and W pre-split into hi/lo bf16 in smem; B frags LDSM'd from smem.
#define LDH 136                       // bf16 row stride (8-half pad)
#define SZ_T (128 * LDH * 2)          // one bf16 tile: 34816 B
#define OFF_XH 0
#define OFF_XL (SZ_T)
#define OFF_WH (2 * SZ_T)
#define OFF_WL (3 * SZ_T)
#define OFF_BI (4 * SZ_T)             // float [16][128] bias tile
#define SMEM_GEMM (OFF_BI + 16 * 128 * 4)   // 147456 B

__device__ __forceinline__ uint2 pack_split4(float4 v, uint2& lo) {
    __nv_bfloat16 h0 = __float2bfloat16_rn(v.x);
    __nv_bfloat16 h1 = __float2bfloat16_rn(v.y);
    __nv_bfloat16 h2 = __float2bfloat16_rn(v.z);
    __nv_bfloat16 h3 = __float2bfloat16_rn(v.w);
    __nv_bfloat16 l0 = __float2bfloat16_rn(v.x - __bfloat162float(h0));
    __nv_bfloat16 l1 = __float2bfloat16_rn(v.y - __bfloat162float(h1));
    __nv_bfloat16 l2 = __float2bfloat16_rn(v.z - __bfloat162float(h2));
    __nv_bfloat16 l3 = __float2bfloat16_rn(v.w - __bfloat162float(h3));
    uint2 hi;
    hi.x = (unsigned)(*(unsigned short*)&h0) | ((unsigned)(*(unsigned short*)&h1) << 16);
    hi.y = (unsigned)(*(unsigned short*)&h2) | ((unsigned)(*(unsigned short*)&h3) << 16);
    lo.x = (unsigned)(*(unsigned short*)&l0) | ((unsigned)(*(unsigned short*)&l1) << 16);
    lo.y = (unsigned)(*(unsigned short*)&l2) | ((unsigned)(*(unsigned short*)&l3) << 16);
    return hi;
}

__global__ void __launch_bounds__(256, 1)
k_gemm_wmma(const float* __restrict__ xin, int layer,
            const float* __restrict__ qw, const float* __restrict__ qb,
            const float* __restrict__ kw, const float* __restrict__ kb,
            const float* __restrict__ vw, const float* __restrict__ vb,
            int N) {
    extern __shared__ char smem[];
    const float* X = layer ? g_H : xin;
    int wsel = blockIdx.y;
    const float* W  = (wsel == 0) ? qw : (wsel == 1) ? kw : vw;
    const float* Bb = (wsel == 0) ? qb : (wsel == 1) ? kb : vb;

    int tid = threadIdx.x;
    int wm = tid >> 5;                 // warp row tile 0..7
    int lane = tid & 31;
    int m0 = blockIdx.x * 128;

    __nv_bfloat16* sXH = (__nv_bfloat16*)(smem + OFF_XH);
    __nv_bfloat16* sXL = (__nv_bfloat16*)(smem + OFF_XL);
    __nv_bfloat16* sWH = (__nv_bfloat16*)(smem + OFF_WH);
    __nv_bfloat16* sWL = (__nv_bfloat16*)(smem + OFF_WL);
    float*         sBi = (float*)(smem + OFF_BI);

    // stage + split X tile and W (4096 float4 chunks each, 16/thread)
    for (int t = tid; t < 128 * 32; t += 256) {
        int r = t >> 5, c = (t & 31) << 2;
        float4 v = make_float4(0.f, 0.f, 0.f, 0.f);
        if (m0 + r < N) v = *(const float4*)(X + (size_t)(m0 + r) * D + c);
        uint2 lo, hi = pack_split4(v, lo);
        *(uint2*)(sXH + r * LDH + c) = hi;
        *(uint2*)(sXL + r * LDH + c) = lo;

        float4 w = *(const float4*)(W + (size_t)r * D + c);
        hi = pack_split4(w, lo);
        *(uint2*)(sWH + r * LDH + c) = hi;
        *(uint2*)(sWL + r * LDH + c) = lo;
    }
    // bias tile replicated over 16 rows
    for (int t = tid; t < 16 * 32; t += 256) {
        int r = t >> 5, c = (t & 31) << 2;
        *(float4*)(sBi + r * 128 + c) = *(const float4*)(Bb + c);
    }
    __syncthreads();

    wmma::fragment<wmma::accumulator, 16, 16, 16, float> acc[8];
#pragma unroll
    for (int n = 0; n < 8; n++)
        wmma::load_matrix_sync(acc[n], sBi + n * 16, 128, wmma::mem_row_major);

#pragma unroll
    for (int k0 = 0; k0 < 128; k0 += 16) {
        wmma::fragment<wmma::matrix_a, 16, 16, 16, __nv_bfloat16, wmma::row_major> aH, aL;
        wmma::load_matrix_sync(aH, sXH + wm * 16 * LDH + k0, LDH);
        wmma::load_matrix_sync(aL, sXL + wm * 16 * LDH + k0, LDH);
#pragma unroll
        for (int n = 0; n < 8; n++) {
            // B[k][nl] = W[n*16+nl][k] -> col_major, ld=LDH
            wmma::fragment<wmma::matrix_b, 16, 16, 16, __nv_bfloat16, wmma::col_major> bH, bL;
            wmma::load_matrix_sync(bH, sWH + n * 16 * LDH + k0, LDH);
            wmma::load_matrix_sync(bL, sWL + n * 16 * LDH + k0, LDH);
            wmma::mma_sync(acc[n], aH, bH, acc[n]);
            wmma::mma_sync(acc[n], aH, bL, acc[n]);
            wmma::mma_sync(acc[n], aL, bH, acc[n]);
        }
    }

    __syncthreads();                   // done reading sXH/sXL: reuse as scratch
    float* scr = (float*)smem;         // [128][128] fp32 scratch (64 KB < 2*SZ_T)
#pragma unroll
    for (int n = 0; n < 8; n++)
        wmma::store_matrix_sync(scr + (wm * 16) * 128 + n * 16, acc[n], 128,
                                wmma::mem_row_major);
    __syncwarp();

    // guarded convert-copy: each warp owns its 16 rows
    for (int t = lane; t < 16 * 32; t += 32) {
        int r = t >> 5, c = (t & 31) << 2;
        int gr = m0 + wm * 16 + r;
        if (gr >= N) continue;
        float4 o = *(float4*)(scr + (wm * 16 + r) * 128 + c);
        if (wsel == 0) {
            *(float4*)(g_Q + (size_t)gr * D + c) = o;
        } else {
            __half2 h01 = __floats2half2_rn(o.x, o.y);
            __half2 h23 = __floats2half2_rn(o.z, o.w);
            uint2 pk;
            pk.x = *(unsigned*)&h01;
            pk.y = *(unsigned*)&h23;
            char* base = (char*)g_KVh + (size_t)gr * 512
                       + ((c >> 2) << 4) + (wsel == 2 ? 8 : 0);
            *(uint2*)base = pk;
        }
    }
}

// ---------------- fused attention: warp per dst node, online softmax ------
// ONE LDG.128 per edge: lane i reads 16 B = {K[4i..4i+3], V[4i..4i+3]} halves.
__global__ void k_attn(float* __restrict__ dout, int layer, int N) {
    int gw = (blockIdx.x * blockDim.x + threadIdx.x) >> 5;
    int lane = threadIdx.x & 31;
    if (gw >= N) return;

    float* outp = layer ? dout : g_H;

    int beg = g_start[gw], end = g_start[gw + 1];
    float4 q = ((const float4*)(g_Q + (size_t)gw * D))[lane];

    float m = -CUDART_INF_F, s = 0.0f;
    float4 acc = make_float4(0.f, 0.f, 0.f, 0.f);

    uint4 kvf;
    if (beg < end)
        kvf = ((const uint4*)((const char*)g_KVh + (size_t)g_csr_src[beg] * 512))[lane];

    for (int e = beg; e < end; e++) {
        uint4 kvc = kvf;
        if (e + 1 < end)                         // prefetch next edge
            kvf = ((const uint4*)((const char*)g_KVh + (size_t)g_csr_src[e + 1] * 512))[lane];

        float2 k01 = __half22float2(*(__half2*)&kvc.x);
        float2 k23 = __half22float2(*(__half2*)&kvc.y);
        float2 v01 = __half22float2(*(__half2*)&kvc.z);
        float2 v23 = __half22float2(*(__half2*)&kvc.w);

        float p = k01.x * q.x + k01.y * q.y + k23.x * q.z + k23.y * q.w;
#pragma unroll
        for (int o = 16; o; o >>= 1) p += __shfl_xor_sync(0xFFFFFFFFu, p, o);
        p *= 0.08838834764831845f;               // 1/sqrt(128)

        float mn = fmaxf(m, p);
        float c  = __expf(m - mn);               // exp(-inf)=0 on first edge
        float ep = __expf(p - mn);
        s = s * c + ep;
        acc.x = acc.x * c + ep * v01.x;
        acc.y = acc.y * c + ep * v01.y;
        acc.z = acc.z * c + ep * v23.x;
        acc.w = acc.w * c + ep * v23.y;
        m = mn;
    }

    float inv = (s > 0.0f) ? 1.0f / s : 0.0f;    // deg==0 -> zeros (matches ref)
    float4 o = make_float4(acc.x * inv, acc.y * inv, acc.z * inv, acc.w * inv);
    if (!layer) {                                 // ELU fused into layer-1 epilogue
        o.x = (o.x > 0.f) ? o.x : expm1f(o.x);
        o.y = (o.y > 0.f) ? o.y : expm1f(o.y);
        o.z = (o.z > 0.f) ? o.z : expm1f(o.z);
        o.w = (o.w > 0.f) ? o.w : expm1f(o.w);
    }
    ((float4*)(outp + (size_t)gw * D))[lane] = o;
}

// ---------------- launch: fork CSR build alongside GEMM-1 ----------------
extern "C" void kernel_launch(void* const* d_in, const int* in_sizes, int n_in,
                              void* d_out, int out_size) {
    const float* x   = (const float*)d_in[0];
    const void*  ei  = d_in[1];
    const float* q1w = (const float*)d_in[2];  const float* q1b = (const float*)d_in[3];
    const float* k1w = (const float*)d_in[4];  const float* k1b = (const float*)d_in[5];
    const float* v1w = (const float*)d_in[6];  const float* v1b = (const float*)d_in[7];
    const float* q2w = (const float*)d_in[8];  const float* q2b = (const float*)d_in[9];
    const float* k2w = (const float*)d_in[10]; const float* k2b = (const float*)d_in[11];
    const float* v2w = (const float*)d_in[12]; const float* v2b = (const float*)d_in[13];

    int N = in_sizes[0] / D;
    int E = in_sizes[1] / 2;
    float* out = (float*)d_out;

    cudaFuncSetAttribute(k_gemm_wmma, cudaFuncAttributeMaxDynamicSharedMemorySize, SMEM_GEMM);

    int eb = (E + 255) / 256;
    int nb = (N + 255) / 256;

    cudaStream_t s2;
    cudaEvent_t evFork, evJoin;
    cudaStreamCreateWithFlags(&s2, cudaStreamNonBlocking);
    cudaEventCreateWithFlags(&evFork, cudaEventDisableTiming);
    cudaEventCreateWithFlags(&evJoin, cudaEventDisableTiming);

    // fork: CSR build on s2 (depends only on edge_index)
    cudaEventRecord(evFork, 0);
    cudaStreamWaitEvent(s2, evFork, 0);
    k_init_csr<<<nb, 256, 0, s2>>>((const unsigned*)ei, N);
    k_convert<<<eb, 256, 0, s2>>>(ei, E);
    k_scan<<<1, 1024, 0, s2>>>(N);
    k_scatter<<<eb, 256, 0, s2>>>(E);
    cudaEventRecord(evJoin, s2);

    dim3 ggrid((N + 127) / 128, 3);
    int ab = (N * 32 + 63) / 64;

    // GEMM-1 (wmma bf16 split) runs concurrently with the CSR build
    k_gemm_wmma<<<ggrid, 256, SMEM_GEMM>>>(x, 0, q1w, q1b, k1w, k1b, v1w, v1b, N);

    // join: attention needs both
    cudaStreamWaitEvent(0, evJoin, 0);
    k_attn<<<ab, 64>>>(out, 0, N);

    // layer 2
    k_gemm_wmma<<<ggrid, 256, SMEM_GEMM>>>(x, 1, q2w, q2b, k2w, k2b, v2w, v2b, N);
    k_attn<<<ab, 64>>>(out, 1, N);
}

// round 14
// speedup vs baseline: 1.1972x; 1.1972x over previous
#include <cuda_runtime.h>
#include <cuda_fp16.h>
#include <cuda_bf16.h>
#include <math_constants.h>
#include <mma.h>
#include <cstdint>

using namespace nvcuda;

#define D     128
#define NMAX  50000
#define EMAX  1600000

// ---------------- device scratch (allocation-free, static) ----------------
__device__ int g_is64;
__device__ int g_src[EMAX];
__device__ int g_dst[EMAX];
__device__ __align__(16) int g_deg[NMAX + 4];
__device__ __align__(16) int g_start[NMAX + 4];
__device__ __align__(16) int g_cursor[NMAX + 4];
__device__ int g_csr_src[EMAX];

__device__ __align__(256) float  g_Q[(size_t)NMAX * D];      // [N,128] fp32
// fp16 K|V lane-interleaved: row = 32 chunks of 16B; chunk i = {K[4i..4i+3], V[4i..4i+3]}
__device__ __align__(256) __half g_KVh[(size_t)NMAX * 256];  // 512 B/row
// pre-split GEMM inputs (hi/lo bf16)
__device__ __align__(256) __nv_bfloat16 g_XH[(size_t)NMAX * D];
__device__ __align__(256) __nv_bfloat16 g_XL[(size_t)NMAX * D];
__device__ __align__(256) __nv_bfloat16 g_WH[6 * D * D];
__device__ __align__(256) __nv_bfloat16 g_WL[6 * D * D];

// ---------------- helpers ----------------
__device__ __forceinline__ uint2 pack_split4(float4 v, uint2& lo) {
    __nv_bfloat16 h0 = __float2bfloat16_rn(v.x);
    __nv_bfloat16 h1 = __float2bfloat16_rn(v.y);
    __nv_bfloat16 h2 = __float2bfloat16_rn(v.z);
    __nv_bfloat16 h3 = __float2bfloat16_rn(v.w);
    __nv_bfloat16 l0 = __float2bfloat16_rn(v.x - __bfloat162float(h0));
    __nv_bfloat16 l1 = __float2bfloat16_rn(v.y - __bfloat162float(h1));
    __nv_bfloat16 l2 = __float2bfloat16_rn(v.z - __bfloat162float(h2));
    __nv_bfloat16 l3 = __float2bfloat16_rn(v.w - __bfloat162float(h3));
    uint2 hi;
    hi.x = (unsigned)(*(unsigned short*)&h0) | ((unsigned)(*(unsigned short*)&h1) << 16);
    hi.y = (unsigned)(*(unsigned short*)&h2) | ((unsigned)(*(unsigned short*)&h3) << 16);
    lo.x = (unsigned)(*(unsigned short*)&l0) | ((unsigned)(*(unsigned short*)&l1) << 16);
    lo.y = (unsigned)(*(unsigned short*)&l2) | ((unsigned)(*(unsigned short*)&l3) << 16);
    return hi;
}

// ---------------- pre-split kernels ----------------
__global__ void k_split_w(const float* __restrict__ w0, const float* __restrict__ w1,
                          const float* __restrict__ w2, const float* __restrict__ w3,
                          const float* __restrict__ w4, const float* __restrict__ w5) {
    int i = blockIdx.x * blockDim.x + threadIdx.x;   // 4 floats per thread
    if (i >= 6 * D * D / 4) return;
    int m = i / (D * D / 4);
    int off = (i % (D * D / 4)) * 4;
    const float* W = (m == 0) ? w0 : (m == 1) ? w1 : (m == 2) ? w2
                   : (m == 3) ? w3 : (m == 4) ? w4 : w5;
    float4 v = *(const float4*)(W + off);
    uint2 lo, hi = pack_split4(v, lo);
    *(uint2*)(g_WH + m * D * D + off) = hi;
    *(uint2*)(g_WL + m * D * D + off) = lo;
}

__global__ void k_split_x(const float* __restrict__ x, int n4) {   // n4 = N*D/4
    int i = blockIdx.x * blockDim.x + threadIdx.x;
    if (i >= n4) return;
    float4 v = *(const float4*)(x + i * 4);
    uint2 lo, hi = pack_split4(v, lo);
    *(uint2*)(g_XH + i * 4) = hi;
    *(uint2*)(g_XL + i * 4) = lo;
}

// ---------------- CSR build ----------------
__global__ void k_init_csr(const unsigned* __restrict__ ei, int N) {
    int i = blockIdx.x * blockDim.x + threadIdx.x;
    if (i < N) g_deg[i] = 0;
    if (i == 0) {
        int is64 = 1;
        for (int j = 0; j < 64; j++)
            if (ei[2 * j + 1] != 0u) is64 = 0;
        g_is64 = is64;
    }
}

__global__ void k_convert(const void* __restrict__ ei, int E) {
    int i = blockIdx.x * blockDim.x + threadIdx.x;
    if (i >= E) return;
    int s, d;
    if (g_is64) {
        const long long* p = (const long long*)ei;
        s = (int)p[i];
        d = (int)p[(size_t)E + i];
    } else {
        const int* p = (const int*)ei;
        s = p[i];
        d = p[E + i];
    }
    g_src[i] = s;
    g_dst[i] = d;
    atomicAdd(&g_deg[d], 1);
}

__global__ void k_scan(int N) {
    __shared__ int warp_sums[32];
    __shared__ int s_carry;
    int tid = threadIdx.x, lane = tid & 31, wid = tid >> 5;
    if (tid == 0) s_carry = 0;
    __syncthreads();

    const int TILE = 4096;
    for (int base = 0; base < N; base += TILE) {
        int idx = base + tid * 4;
        int4 v = make_int4(0, 0, 0, 0);
        if (idx + 3 < N) v = *(const int4*)&g_deg[idx];
        else {
            if (idx + 0 < N) v.x = g_deg[idx + 0];
            if (idx + 1 < N) v.y = g_deg[idx + 1];
            if (idx + 2 < N) v.z = g_deg[idx + 2];
            if (idx + 3 < N) v.w = g_deg[idx + 3];
        }
        int t0 = v.x, t1 = t0 + v.y, t2 = t1 + v.z, t3 = t2 + v.w;
        int inc = t3;
#pragma unroll
        for (int o = 1; o < 32; o <<= 1) {
            int n = __shfl_up_sync(0xFFFFFFFFu, inc, o);
            if (lane >= o) inc += n;
        }
        if (lane == 31) warp_sums[wid] = inc;
        __syncthreads();
        if (wid == 0) {
            int ws = warp_sums[lane];
#pragma unroll
            for (int o = 1; o < 32; o <<= 1) {
                int n = __shfl_up_sync(0xFFFFFFFFu, ws, o);
                if (lane >= o) ws += n;
            }
            warp_sums[lane] = ws;
        }
        __syncthreads();
        int warp_off = wid ? warp_sums[wid - 1] : 0;
        int e0 = s_carry + warp_off + (inc - t3);
        int tile_total = warp_sums[31];

        if (idx + 3 < N) {
            int4 e = make_int4(e0, e0 + t0, e0 + t1, e0 + t2);
            *(int4*)&g_start[idx]  = e;
            *(int4*)&g_cursor[idx] = e;
        } else {
            if (idx + 0 < N) { g_start[idx + 0] = e0;      g_cursor[idx + 0] = e0;      }
            if (idx + 1 < N) { g_start[idx + 1] = e0 + t0; g_cursor[idx + 1] = e0 + t0; }
            if (idx + 2 < N) { g_start[idx + 2] = e0 + t1; g_cursor[idx + 2] = e0 + t1; }
            if (idx + 3 < N) { g_start[idx + 3] = e0 + t2; g_cursor[idx + 3] = e0 + t2; }
        }
        __syncthreads();
        if (tid == 0) s_carry += tile_total;
        __syncthreads();
    }
    if (tid == 0) g_start[N] = s_carry;
}

__global__ void k_scatter(int E) {
    int i = blockIdx.x * blockDim.x + threadIdx.x;
    if (i >= E) return;
    int d = g_dst[i];
    int pos = atomicAdd(&g_cursor[d], 1);
    g_csr_src[pos] = g_src[i];
}

// ---------------- fused 3-output wmma GEMM: {Q,K,V} = X @ W^T + b --------
// One CTA: 128-row X tile staged once (pre-split bf16), loop over 3 weights.
#define LDH 136
#define SZ_T (128 * LDH * 2)          // 34816 B per bf16 tile
#define OFF_XH 0
#define OFF_XL (SZ_T)
#define OFF_W  (2 * SZ_T)             // WH (also output scratch with WL)
#define OFF_WL (3 * SZ_T)
#define OFF_BI (4 * SZ_T)
#define SMEM_GEMM (OFF_BI + 16 * 128 * 4)   // 147456 B

__global__ void __launch_bounds__(256, 1)
k_gemm3(int layer, const float* __restrict__ qb, const float* __restrict__ kb,
        const float* __restrict__ vb, int N) {
    extern __shared__ char smem[];
    __nv_bfloat16* sXH = (__nv_bfloat16*)(smem + OFF_XH);
    __nv_bfloat16* sXL = (__nv_bfloat16*)(smem + OFF_XL);
    __nv_bfloat16* sWH = (__nv_bfloat16*)(smem + OFF_W);
    __nv_bfloat16* sWL = (__nv_bfloat16*)(smem + OFF_WL);
    float*         sBi = (float*)(smem + OFF_BI);
    float*         scr = (float*)(smem + OFF_W);   // 64 KB scratch post-MMA

    int tid = threadIdx.x, wm = tid >> 5, lane = tid & 31;
    int m0 = blockIdx.x * 128;

    // stage X tile (pure copies of pre-split bf16; zero-pad OOB rows)
    for (int t = tid; t < 128 * 16; t += 256) {
        int r = t >> 4, c = (t & 15) << 3;         // 8 halves per uint4
        uint4 h = make_uint4(0, 0, 0, 0), l = make_uint4(0, 0, 0, 0);
        if (m0 + r < N) {
            h = *(const uint4*)(g_XH + (size_t)(m0 + r) * D + c);
            l = *(const uint4*)(g_XL + (size_t)(m0 + r) * D + c);
        }
        *(uint4*)(sXH + r * LDH + c) = h;
        *(uint4*)(sXL + r * LDH + c) = l;
    }

    for (int o = 0; o < 3; o++) {
        const float* Bb = (o == 0) ? qb : (o == 1) ? kb : vb;
        const __nv_bfloat16* WH = g_WH + (size_t)(layer * 3 + o) * D * D;
        const __nv_bfloat16* WL = g_WL + (size_t)(layer * 3 + o) * D * D;

        // stage W hi/lo + bias
        for (int t = tid; t < 128 * 16; t += 256) {
            int r = t >> 4, c = (t & 15) << 3;
            *(uint4*)(sWH + r * LDH + c) = *(const uint4*)(WH + r * D + c);
            *(uint4*)(sWL + r * LDH + c) = *(const uint4*)(WL + r * D + c);
        }
        for (int t = tid; t < 16 * 32; t += 256) {
            int r = t >> 5, c = (t & 31) << 2;
            *(float4*)(sBi + r * 128 + c) = *(const float4*)(Bb + c);
        }
        __syncthreads();

        wmma::fragment<wmma::accumulator, 16, 16, 16, float> acc[8];
#pragma unroll
        for (int n = 0; n < 8; n++)
            wmma::load_matrix_sync(acc[n], sBi + n * 16, 128, wmma::mem_row_major);

#pragma unroll
        for (int k0 = 0; k0 < 128; k0 += 16) {
            wmma::fragment<wmma::matrix_a, 16, 16, 16, __nv_bfloat16, wmma::row_major> aH, aL;
            wmma::load_matrix_sync(aH, sXH + wm * 16 * LDH + k0, LDH);
            wmma::load_matrix_sync(aL, sXL + wm * 16 * LDH + k0, LDH);
#pragma unroll
            for (int n = 0; n < 8; n++) {
                wmma::fragment<wmma::matrix_b, 16, 16, 16, __nv_bfloat16, wmma::col_major> bH, bL;
                wmma::load_matrix_sync(bH, sWH + n * 16 * LDH + k0, LDH);
                wmma::load_matrix_sync(bL, sWL + n * 16 * LDH + k0, LDH);
                wmma::mma_sync(acc[n], aH, bH, acc[n]);
                wmma::mma_sync(acc[n], aH, bL, acc[n]);
                wmma::mma_sync(acc[n], aL, bH, acc[n]);
            }
        }
        __syncthreads();                 // all W reads done -> scr may overwrite

        // frags -> scratch (each warp owns its 16 rows)
#pragma unroll
        for (int n = 0; n < 8; n++)
            wmma::store_matrix_sync(scr + (wm * 16) * 128 + n * 16, acc[n], 128,
                                    wmma::mem_row_major);
        __syncwarp();

        for (int t = lane; t < 16 * 32; t += 32) {
            int r = t >> 5, c = (t & 31) << 2;
            int gr = m0 + wm * 16 + r;
            if (gr >= N) continue;
            float4 v = *(float4*)(scr + (wm * 16 + r) * 128 + c);
            if (o == 0) {
                *(float4*)(g_Q + (size_t)gr * D + c) = v;
            } else {
                __half2 h01 = __floats2half2_rn(v.x, v.y);
                __half2 h23 = __floats2half2_rn(v.z, v.w);
                uint2 pk;
                pk.x = *(unsigned*)&h01;
                pk.y = *(unsigned*)&h23;
                char* base = (char*)g_KVh + (size_t)gr * 512
                           + ((c >> 2) << 4) + (o == 2 ? 8 : 0);
                *(uint2*)base = pk;
            }
        }
        __syncthreads();                 // before next W staging reuses buffers
    }
}

// ---------------- fused attention: warp per dst node, online softmax ------
// layer 0: write ELU(H) as split bf16 into g_XH/g_XL (feeds gemm layer 2).
// layer 1: write fp32 to dout.
__global__ void k_attn(float* __restrict__ dout, int layer, int N) {
    int gw = (blockIdx.x * blockDim.x + threadIdx.x) >> 5;
    int lane = threadIdx.x & 31;
    if (gw >= N) return;

    int beg = g_start[gw], end = g_start[gw + 1];
    float4 q = ((const float4*)(g_Q + (size_t)gw * D))[lane];

    float m = -CUDART_INF_F, s = 0.0f;
    float4 acc = make_float4(0.f, 0.f, 0.f, 0.f);

    uint4 kvf;
    if (beg < end)
        kvf = ((const uint4*)((const char*)g_KVh + (size_t)g_csr_src[beg] * 512))[lane];

    for (int e = beg; e < end; e++) {
        uint4 kvc = kvf;
        if (e + 1 < end)                         // prefetch next edge
            kvf = ((const uint4*)((const char*)g_KVh + (size_t)g_csr_src[e + 1] * 512))[lane];

        float2 k01 = __half22float2(*(__half2*)&kvc.x);
        float2 k23 = __half22float2(*(__half2*)&kvc.y);
        float2 v01 = __half22float2(*(__half2*)&kvc.z);
        float2 v23 = __half22float2(*(__half2*)&kvc.w);

        float p = k01.x * q.x + k01.y * q.y + k23.x * q.z + k23.y * q.w;
#pragma unroll
        for (int o = 16; o; o >>= 1) p += __shfl_xor_sync(0xFFFFFFFFu, p, o);
        p *= 0.08838834764831845f;               // 1/sqrt(128)

        float mn = fmaxf(m, p);
        float c  = __expf(m - mn);               // exp(-inf)=0 on first edge
        float ep = __expf(p - mn);
        s = s * c + ep;
        acc.x = acc.x * c + ep * v01.x;
        acc.y = acc.y * c + ep * v01.y;
        acc.z = acc.z * c + ep * v23.x;
        acc.w = acc.w * c + ep * v23.y;
        m = mn;
    }

    float inv = (s > 0.0f) ? 1.0f / s : 0.0f;    // deg==0 -> zeros (matches ref)
    float4 o = make_float4(acc.x * inv, acc.y * inv, acc.z * inv, acc.w * inv);
    if (!layer) {
        o.x = (o.x > 0.f) ? o.x : expm1f(o.x);   // ELU fused
        o.y = (o.y > 0.f) ? o.y : expm1f(o.y);
        o.z = (o.z > 0.f) ? o.z : expm1f(o.z);
        o.w = (o.w > 0.f) ? o.w : expm1f(o.w);
        uint2 lo, hi = pack_split4(o, lo);       // split for layer-2 GEMM
        *(uint2*)(g_XH + (size_t)gw * D + lane * 4) = hi;
        *(uint2*)(g_XL + (size_t)gw * D + lane * 4) = lo;
    } else {
        ((float4*)(dout + (size_t)gw * D))[lane] = o;
    }
}

// ---------------- launch ----------------
extern "C" void kernel_launch(void* const* d_in, const int* in_sizes, int n_in,
                              void* d_out, int out_size) {
    const float* x   = (const float*)d_in[0];
    const void*  ei  = d_in[1];
    const float* q1w = (const float*)d_in[2];  const float* q1b = (const float*)d_in[3];
    const float* k1w = (const float*)d_in[4];  const float* k1b = (const float*)d_in[5];
    const float* v1w = (const float*)d_in[6];  const float* v1b = (const float*)d_in[7];
    const float* q2w = (const float*)d_in[8];  const float* q2b = (const float*)d_in[9];
    const float* k2w = (const float*)d_in[10]; const float* k2b = (const float*)d_in[11];
    const float* v2w = (const float*)d_in[12]; const float* v2b = (const float*)d_in[13];

    int N = in_sizes[0] / D;
    int E = in_sizes[1] / 2;
    float* out = (float*)d_out;

    cudaFuncSetAttribute(k_gemm3, cudaFuncAttributeMaxDynamicSharedMemorySize, SMEM_GEMM);

    int eb = (E + 255) / 256;
    int nb = (N + 255) / 256;

    cudaStream_t s2;
    cudaEvent_t evFork, evJoin;
    cudaStreamCreateWithFlags(&s2, cudaStreamNonBlocking);
    cudaEventCreateWithFlags(&evFork, cudaEventDisableTiming);
    cudaEventCreateWithFlags(&evJoin, cudaEventDisableTiming);

    // fork: CSR build on s2 (depends only on edge_index)
    cudaEventRecord(evFork, 0);
    cudaStreamWaitEvent(s2, evFork, 0);
    k_init_csr<<<nb, 256, 0, s2>>>((const unsigned*)ei, N);
    k_convert<<<eb, 256, 0, s2>>>(ei, E);
    k_scan<<<1, 1024, 0, s2>>>(N);
    k_scatter<<<eb, 256, 0, s2>>>(E);
    cudaEventRecord(evJoin, s2);

    // main: pre-splits then GEMM-1 (overlapped with CSR build)
    k_split_w<<<(6 * D * D / 4 + 255) / 256, 256>>>(q1w, k1w, v1w, q2w, k2w, v2w);
    k_split_x<<<(N * D / 4 + 255) / 256, 256>>>(x, N * D / 4);

    int gg = (N + 127) / 128;
    int ab = (N * 32 + 63) / 64;

    k_gemm3<<<gg, 256, SMEM_GEMM>>>(0, q1b, k1b, v1b, N);

    // join: attention needs CSR + Q/KV
    cudaStreamWaitEvent(0, evJoin, 0);
    k_attn<<<ab, 64>>>(out, 0, N);

    // layer 2
    k_gemm3<<<gg, 256, SMEM_GEMM>>>(1, q2b, k2b, v2b, N);
    k_attn<<<ab, 64>>>(out, 1, N);
}